// round 15
// baseline (speedup 1.0000x reference)
#include <cuda_runtime.h>

// StandardPershomReadout — quad-point register blocking (LDS.128), full unroll,
// warp0-only drain epilogue.
// f(d) = 1/(1+d) - 1/(1+||r|-d|) = (b-a)/(a*b),  a=1+d, b=1+|u|, u=d-|r|.

#define KC    64
#define TPB   128               // 4 warps
#define PTS   128               // points per tile
#define PPT   (PTS / 4)         // 32 points per warp
#define NT0   (128 * (4096 / PTS))   // 4096 sec0 tiles (32 chunks per b)
#define NTE   (128 * (1024 / PTS))   // 1024 tiles per ess section (8 chunks per b)
#define NTILES (NT0 + 2 * NTE)       // 6144

typedef unsigned long long ull;

__device__ float        g_part[NTILES][KC];   // per-block private partials (plain stores)
__device__ unsigned int g_count[128 * 3];     // zero-init; reset by drain warp

#define ADD2(o,a,b)   asm("add.rn.f32x2 %0, %1, %2;" : "=l"(o) : "l"(a), "l"(b))
#define MUL2(o,a,b)   asm("mul.rn.f32x2 %0, %1, %2;" : "=l"(o) : "l"(a), "l"(b))
#define FMA2(o,a,b,c) asm("fma.rn.f32x2 %0, %1, %2, %3;" : "=l"(o) : "l"(a), "l"(b), "l"(c))
#define ABS2(o,a)     asm("and.b64 %0, %1, 0x7FFFFFFF7FFFFFFF;" : "=l"(o) : "l"(a))

__device__ __forceinline__ ull pk2(float lo, float hi) {
    ull r; asm("mov.b64 %0, {%1, %2};" : "=l"(r) : "f"(lo), "f"(hi)); return r;
}
__device__ __forceinline__ void upk2(ull v, float& lo, float& hi) {
    asm("mov.b64 {%0, %1}, %2;" : "=f"(lo), "=f"(hi) : "l"(v));
}
__device__ __forceinline__ float frcp(float x) {
    float r; asm("rcp.approx.ftz.f32 %0, %1;" : "=f"(r) : "f"(x)); return r;
}
__device__ __forceinline__ unsigned int atom_add_acq_rel(unsigned int* p, unsigned int v) {
    unsigned int old;
    asm volatile("atom.acq_rel.gpu.global.add.u32 %0, [%1], %2;"
                 : "=r"(old) : "l"(p), "r"(v) : "memory");
    return old;
}

// one center's contribution for a packed point-pair (d2 = packed L1 distances)
__device__ __forceinline__ void hat_accum(ull d2, ull m2, ull nar2, ull one2, ull negone2,
                                          float& acc_lo, float& acc_hi)
{
    ull u2, a2, b2, den2, num2, nm2;
    ADD2(u2, d2, nar2);  ABS2(u2, u2);      // |d - |r||
    ADD2(a2, d2, one2);                     // 1 + d
    ADD2(b2, u2, one2);                     // 1 + |u|
    MUL2(den2, a2, b2);
    FMA2(num2, a2, negone2, b2);            // b - a  ==  |u| - d
    MUL2(nm2, num2, m2);
    float dl, dh, nl, nh;
    upk2(den2, dl, dh); upk2(nm2, nl, nh);
    acc_lo = fmaf(nl, frcp(dl), acc_lo);
    acc_hi = fmaf(nh, frcp(dh), acc_hi);
}

// L1 distance (D=2) for a packed point-pair against one packed (negated) center
__device__ __forceinline__ ull dist2d(ull px, ull py, ull ncx, ull ncy)
{
    ull tx, ty, d2;
    ADD2(tx, px, ncx); ABS2(tx, tx);
    ADD2(ty, py, ncy); ABS2(ty, ty);
    ADD2(d2, tx, ty);
    return d2;
}

__global__ void __launch_bounds__(TPB)
pershom_kernel(const float* __restrict__ h0,  const float* __restrict__ m0,
               const float* __restrict__ h0e, const float* __restrict__ m0e,
               const float* __restrict__ h1e, const float* __restrict__ m1e,
               const float* __restrict__ c0,  const float* __restrict__ r0,
               const float* __restrict__ c0e, const float* __restrict__ r0e,
               const float* __restrict__ c1e, const float* __restrict__ r1e,
               float* __restrict__ out)
{
    __shared__ __align__(16) float sxx[PTS];
    __shared__ __align__(16) float syy[PTS];
    __shared__ __align__(16) float smm[PTS];
    __shared__ __align__(16) float red[KC];

    const int t   = blockIdx.x;
    const int tid = threadIdx.x;

    int b, dim, grp, nchunks, outoff, row0;
    const float *pts, *mask, *centers, *radp;

    if (t < NT0) {
        b = t >> 5; int chunk = t & 31;
        dim = 2; grp = b; nchunks = 32; outoff = 0; row0 = b << 5;
        pts  = h0 + ((size_t)b * 4096 + chunk * PTS) * 2;
        mask = m0 + (size_t)b * 4096 + chunk * PTS;
        centers = c0; radp = r0;
    } else if (t < NT0 + NTE) {
        int r = t - NT0;
        b = r >> 3; int chunk = r & 7;
        dim = 1; grp = 128 + b; nchunks = 8; outoff = KC; row0 = NT0 + (b << 3);
        pts  = h0e + (size_t)b * 1024 + chunk * PTS;
        mask = m0e + (size_t)b * 1024 + chunk * PTS;
        centers = c0e; radp = r0e;
    } else {
        int r = t - NT0 - NTE;
        b = r >> 3; int chunk = r & 7;
        dim = 1; grp = 256 + b; nchunks = 8; outoff = 2 * KC; row0 = NT0 + NTE + (b << 3);
        pts  = h1e + (size_t)b * 1024 + chunk * PTS;
        mask = m1e + (size_t)b * 1024 + chunk * PTS;
        centers = c1e; radp = r1e;
    }

    // Stage SoA (one element per thread at PTS==TPB).
    if (dim == 2) {
        float2 v = ((const float2*)pts)[tid];
        sxx[tid] = v.x; syy[tid] = v.y;
    } else {
        sxx[tid] = pts[tid];
    }
    smm[tid] = mask[tid];
    if (tid < KC) red[tid] = 0.0f;

    const int lane = tid & 31;
    const int team = tid >> 5;               // 4 warp-teams
    const float ar = fabsf(*radp);

    const ull one2    = pk2(1.0f, 1.0f);
    const ull negone2 = pk2(-1.0f, -1.0f);
    const ull nar2    = pk2(-ar, -ar);

    ull ncxA, ncyA = 0, ncxB, ncyB = 0;
    if (dim == 2) {
        float cax = centers[2 * lane],        cay = centers[2 * lane + 1];
        float cbx = centers[2 * (lane + 32)], cby = centers[2 * (lane + 32) + 1];
        ncxA = pk2(-cax, -cax); ncyA = pk2(-cay, -cay);
        ncxB = pk2(-cbx, -cbx); ncyB = pk2(-cby, -cby);
    } else {
        float ca = centers[lane], cb = centers[lane + 32];
        ncxA = pk2(-ca, -ca);
        ncxB = pk2(-cb, -cb);
    }

    __syncthreads();

    float aAl = 0.0f, aAh = 0.0f, aBl = 0.0f, aBh = 0.0f;
    const int base = team * PPT;

    if (dim == 2) {
        #pragma unroll
        for (int i = 0; i < PPT; i += 4) {
            // quad-point: one LDS.128 per array -> two packed point-pairs
            const ulonglong2 vx = *(const ulonglong2*)&sxx[base + i];
            const ulonglong2 vy = *(const ulonglong2*)&syy[base + i];
            const ulonglong2 vm = *(const ulonglong2*)&smm[base + i];
            // center A, pairs 0 and 1 (independent chains)
            hat_accum(dist2d(vx.x, vy.x, ncxA, ncyA), vm.x, nar2, one2, negone2, aAl, aAh);
            hat_accum(dist2d(vx.y, vy.y, ncxA, ncyA), vm.y, nar2, one2, negone2, aAl, aAh);
            // center B, pairs 0 and 1
            hat_accum(dist2d(vx.x, vy.x, ncxB, ncyB), vm.x, nar2, one2, negone2, aBl, aBh);
            hat_accum(dist2d(vx.y, vy.y, ncxB, ncyB), vm.y, nar2, one2, negone2, aBl, aBh);
        }
    } else {
        #pragma unroll
        for (int i = 0; i < PPT; i += 4) {
            const ulonglong2 vx = *(const ulonglong2*)&sxx[base + i];
            const ulonglong2 vm = *(const ulonglong2*)&smm[base + i];
            ull t0, t1;
            ADD2(t0, vx.x, ncxA); ABS2(t0, t0);
            hat_accum(t0, vm.x, nar2, one2, negone2, aAl, aAh);
            ADD2(t1, vx.y, ncxA); ABS2(t1, t1);
            hat_accum(t1, vm.y, nar2, one2, negone2, aAl, aAh);
            ADD2(t0, vx.x, ncxB); ABS2(t0, t0);
            hat_accum(t0, vm.x, nar2, one2, negone2, aBl, aBh);
            ADD2(t1, vx.y, ncxB); ABS2(t1, t1);
            hat_accum(t1, vm.y, nar2, one2, negone2, aBl, aBh);
        }
    }

    // Block reduce: per-warp lanes hit distinct smem addresses (no conflict).
    atomicAdd(&red[lane],      aAl + aAh);
    atomicAdd(&red[lane + 32], aBl + aBh);
    __syncthreads();

    // Warps 1-3 are done: no further CTA barrier, early exit frees their slots.
    if (tid >= 32) return;

    // Warp 0: store private partial row (16 x STG.128, zero contention).
    if (lane < KC / 4)
        ((float4*)g_part[t])[lane] = ((const float4*)red)[lane];
    __syncwarp();                            // order STGs before the release

    unsigned int slast = 0;
    if (lane == 0) {
        unsigned int old = atom_add_acq_rel(&g_count[grp], 1u);
        slast = (old == (unsigned int)(nchunks - 1)) ? 1u : 0u;
    }
    slast = __shfl_sync(0xffffffffu, slast, 0);
    __syncwarp();                            // propagate lane0's acquire

    if (slast) {
        // Drain: each lane sums k=lane and k=lane+32 over the group's rows.
        float v0 = 0.0f, v1 = 0.0f;
        #pragma unroll 8
        for (int c = 0; c < nchunks; ++c) {
            v0 += g_part[row0 + c][lane];
            v1 += g_part[row0 + c][lane + 32];
        }
        out[b * (3 * KC) + outoff + lane]      = v0;
        out[b * (3 * KC) + outoff + lane + 32] = v1;
        if (lane == 0) g_count[grp] = 0u;    // reset for next graph replay
    }
}

extern "C" void kernel_launch(void* const* d_in, const int* in_sizes, int n_in,
                              void* d_out, int out_size)
{
    (void)in_sizes; (void)n_in; (void)out_size;
    const float* h0  = (const float*)d_in[0];
    const float* m0  = (const float*)d_in[1];
    const float* h0e = (const float*)d_in[2];
    const float* m0e = (const float*)d_in[3];
    const float* h1e = (const float*)d_in[4];
    const float* m1e = (const float*)d_in[5];
    const float* c0  = (const float*)d_in[6];
    const float* r0  = (const float*)d_in[7];
    const float* c0e = (const float*)d_in[8];
    const float* r0e = (const float*)d_in[9];
    const float* c1e = (const float*)d_in[10];
    const float* r1e = (const float*)d_in[11];
    float* out = (float*)d_out;

    pershom_kernel<<<NTILES, TPB>>>(h0, m0, h0e, m0e, h1e, m1e,
                                    c0, r0, c0e, r0e, c1e, r1e, out);
}

// round 17
// speedup vs baseline: 1.0013x; 1.0013x over previous
#include <cuda_runtime.h>

// StandardPershomReadout — quad-point inner loop with branch-specialized
// masked/unmasked variants (mask==1 detected per block), warp0-only drain.
// f(d) = 1/(1+d) - 1/(1+||r|-d|) = (b-a)/(a*b),  a=1+d, b=1+|u|, u=d-|r|.

#define KC    64
#define TPB   128               // 4 warps
#define PTS   128               // points per tile
#define PPT   (PTS / 4)         // 32 points per warp
#define NT0   (128 * (4096 / PTS))   // 4096 sec0 tiles (32 chunks per b)
#define NTE   (128 * (1024 / PTS))   // 1024 tiles per ess section (8 chunks per b)
#define NTILES (NT0 + 2 * NTE)       // 6144

typedef unsigned long long ull;

__device__ float        g_part[NTILES][KC];   // per-block private partials (plain stores)
__device__ unsigned int g_count[128 * 3];     // zero-init; reset by drain warp

#define ADD2(o,a,b)   asm("add.rn.f32x2 %0, %1, %2;" : "=l"(o) : "l"(a), "l"(b))
#define MUL2(o,a,b)   asm("mul.rn.f32x2 %0, %1, %2;" : "=l"(o) : "l"(a), "l"(b))
#define FMA2(o,a,b,c) asm("fma.rn.f32x2 %0, %1, %2, %3;" : "=l"(o) : "l"(a), "l"(b), "l"(c))
#define ABS2(o,a)     asm("and.b64 %0, %1, 0x7FFFFFFF7FFFFFFF;" : "=l"(o) : "l"(a))

__device__ __forceinline__ ull pk2(float lo, float hi) {
    ull r; asm("mov.b64 %0, {%1, %2};" : "=l"(r) : "f"(lo), "f"(hi)); return r;
}
__device__ __forceinline__ void upk2(ull v, float& lo, float& hi) {
    asm("mov.b64 {%0, %1}, %2;" : "=f"(lo), "=f"(hi) : "l"(v));
}
__device__ __forceinline__ float frcp(float x) {
    float r; asm("rcp.approx.ftz.f32 %0, %1;" : "=f"(r) : "f"(x)); return r;
}
__device__ __forceinline__ unsigned int atom_add_acq_rel(unsigned int* p, unsigned int v) {
    unsigned int old;
    asm volatile("atom.acq_rel.gpu.global.add.u32 %0, [%1], %2;"
                 : "=r"(old) : "l"(p), "r"(v) : "memory");
    return old;
}

// one center's contribution for a packed point-pair (d2 = packed L1 distances).
// MASKED=false skips the mask multiply (valid when all masks are exactly 1.0f).
template <bool MASKED>
__device__ __forceinline__ void hat_accum(ull d2, ull m2, ull nar2, ull one2, ull negone2,
                                          float& acc_lo, float& acc_hi)
{
    ull u2, a2, b2, den2, num2;
    ADD2(u2, d2, nar2);  ABS2(u2, u2);      // |d - |r||
    ADD2(a2, d2, one2);                     // 1 + d
    ADD2(b2, u2, one2);                     // 1 + |u|
    MUL2(den2, a2, b2);
    FMA2(num2, a2, negone2, b2);            // b - a  ==  |u| - d
    if (MASKED) MUL2(num2, num2, m2);
    float dl, dh, nl, nh;
    upk2(den2, dl, dh); upk2(num2, nl, nh);
    acc_lo = fmaf(nl, frcp(dl), acc_lo);
    acc_hi = fmaf(nh, frcp(dh), acc_hi);
}

// L1 distance (D=2) for a packed point-pair against one packed (negated) center
__device__ __forceinline__ ull dist2d(ull px, ull py, ull ncx, ull ncy)
{
    ull tx, ty, d2;
    ADD2(tx, px, ncx); ABS2(tx, tx);
    ADD2(ty, py, ncy); ABS2(ty, ty);
    ADD2(d2, tx, ty);
    return d2;
}

template <int DIM, bool MASKED>
__device__ __forceinline__ void process_tile(
    const float* sxx, const float* syy, const float* smm, int base,
    ull ncxA, ull ncyA, ull ncxB, ull ncyB,
    ull nar2, ull one2, ull negone2,
    float& aAl, float& aAh, float& aBl, float& aBh)
{
    #pragma unroll 2
    for (int i = 0; i < PPT; i += 4) {
        const ulonglong2 vx = *(const ulonglong2*)&sxx[base + i];
        ulonglong2 vm = {0, 0};
        if (MASKED) vm = *(const ulonglong2*)&smm[base + i];
        if (DIM == 2) {
            const ulonglong2 vy = *(const ulonglong2*)&syy[base + i];
            hat_accum<MASKED>(dist2d(vx.x, vy.x, ncxA, ncyA), vm.x, nar2, one2, negone2, aAl, aAh);
            hat_accum<MASKED>(dist2d(vx.y, vy.y, ncxA, ncyA), vm.y, nar2, one2, negone2, aAl, aAh);
            hat_accum<MASKED>(dist2d(vx.x, vy.x, ncxB, ncyB), vm.x, nar2, one2, negone2, aBl, aBh);
            hat_accum<MASKED>(dist2d(vx.y, vy.y, ncxB, ncyB), vm.y, nar2, one2, negone2, aBl, aBh);
        } else {
            ull t0, t1;
            ADD2(t0, vx.x, ncxA); ABS2(t0, t0);
            hat_accum<MASKED>(t0, vm.x, nar2, one2, negone2, aAl, aAh);
            ADD2(t1, vx.y, ncxA); ABS2(t1, t1);
            hat_accum<MASKED>(t1, vm.y, nar2, one2, negone2, aAl, aAh);
            ADD2(t0, vx.x, ncxB); ABS2(t0, t0);
            hat_accum<MASKED>(t0, vm.x, nar2, one2, negone2, aBl, aBh);
            ADD2(t1, vx.y, ncxB); ABS2(t1, t1);
            hat_accum<MASKED>(t1, vm.y, nar2, one2, negone2, aBl, aBh);
        }
    }
}

__global__ void __launch_bounds__(TPB)
pershom_kernel(const float* __restrict__ h0,  const float* __restrict__ m0,
               const float* __restrict__ h0e, const float* __restrict__ m0e,
               const float* __restrict__ h1e, const float* __restrict__ m1e,
               const float* __restrict__ c0,  const float* __restrict__ r0,
               const float* __restrict__ c0e, const float* __restrict__ r0e,
               const float* __restrict__ c1e, const float* __restrict__ r1e,
               float* __restrict__ out)
{
    __shared__ __align__(16) float sxx[PTS];
    __shared__ __align__(16) float syy[PTS];
    __shared__ __align__(16) float smm[PTS];
    __shared__ __align__(16) float red[KC];
    __shared__ int smasked;

    const int t   = blockIdx.x;
    const int tid = threadIdx.x;

    int b, dim, grp, nchunks, outoff, row0;
    const float *pts, *mask, *centers, *radp;

    if (t < NT0) {
        b = t >> 5; int chunk = t & 31;
        dim = 2; grp = b; nchunks = 32; outoff = 0; row0 = b << 5;
        pts  = h0 + ((size_t)b * 4096 + chunk * PTS) * 2;
        mask = m0 + (size_t)b * 4096 + chunk * PTS;
        centers = c0; radp = r0;
    } else if (t < NT0 + NTE) {
        int r = t - NT0;
        b = r >> 3; int chunk = r & 7;
        dim = 1; grp = 128 + b; nchunks = 8; outoff = KC; row0 = NT0 + (b << 3);
        pts  = h0e + (size_t)b * 1024 + chunk * PTS;
        mask = m0e + (size_t)b * 1024 + chunk * PTS;
        centers = c0e; radp = r0e;
    } else {
        int r = t - NT0 - NTE;
        b = r >> 3; int chunk = r & 7;
        dim = 1; grp = 256 + b; nchunks = 8; outoff = 2 * KC; row0 = NT0 + NTE + (b << 3);
        pts  = h1e + (size_t)b * 1024 + chunk * PTS;
        mask = m1e + (size_t)b * 1024 + chunk * PTS;
        centers = c1e; radp = r1e;
    }

    // Stage SoA; detect non-trivial masks (benign same-value race on smasked).
    if (tid == 0) smasked = 0;
    float mv = mask[tid];
    if (dim == 2) {
        float2 v = ((const float2*)pts)[tid];
        sxx[tid] = v.x; syy[tid] = v.y;
    } else {
        sxx[tid] = pts[tid];
    }
    smm[tid] = mv;
    if (tid < KC) red[tid] = 0.0f;

    const int lane = tid & 31;
    const int team = tid >> 5;               // 4 warp-teams
    const float ar = fabsf(*radp);

    const ull one2    = pk2(1.0f, 1.0f);
    const ull negone2 = pk2(-1.0f, -1.0f);
    const ull nar2    = pk2(-ar, -ar);

    ull ncxA, ncyA = 0, ncxB, ncyB = 0;
    if (dim == 2) {
        float cax = centers[2 * lane],        cay = centers[2 * lane + 1];
        float cbx = centers[2 * (lane + 32)], cby = centers[2 * (lane + 32) + 1];
        ncxA = pk2(-cax, -cax); ncyA = pk2(-cay, -cay);
        ncxB = pk2(-cbx, -cbx); ncyB = pk2(-cby, -cby);
    } else {
        float ca = centers[lane], cb = centers[lane + 32];
        ncxA = pk2(-ca, -ca);
        ncxB = pk2(-cb, -cb);
    }

    if (mv != 1.0f) smasked = 1;   // before barrier; visible to all after it
    __syncthreads();

    float aAl = 0.0f, aAh = 0.0f, aBl = 0.0f, aBh = 0.0f;
    const int base = team * PPT;
    const bool masked = (smasked != 0);

    if (dim == 2) {
        if (masked)
            process_tile<2, true >(sxx, syy, smm, base, ncxA, ncyA, ncxB, ncyB,
                                   nar2, one2, negone2, aAl, aAh, aBl, aBh);
        else
            process_tile<2, false>(sxx, syy, smm, base, ncxA, ncyA, ncxB, ncyB,
                                   nar2, one2, negone2, aAl, aAh, aBl, aBh);
    } else {
        if (masked)
            process_tile<1, true >(sxx, syy, smm, base, ncxA, ncyA, ncxB, ncyB,
                                   nar2, one2, negone2, aAl, aAh, aBl, aBh);
        else
            process_tile<1, false>(sxx, syy, smm, base, ncxA, ncyA, ncxB, ncyB,
                                   nar2, one2, negone2, aAl, aAh, aBl, aBh);
    }

    // Block reduce: per-warp lanes hit distinct smem addresses (no conflict).
    atomicAdd(&red[lane],      aAl + aAh);
    atomicAdd(&red[lane + 32], aBl + aBh);
    __syncthreads();

    // Warps 1-3 are done: no further CTA barrier, early exit frees their slots.
    if (tid >= 32) return;

    // Warp 0: store private partial row (16 x STG.128, zero contention).
    if (lane < KC / 4)
        ((float4*)g_part[t])[lane] = ((const float4*)red)[lane];
    __syncwarp();                            // order STGs before the release

    unsigned int slast = 0;
    if (lane == 0) {
        unsigned int old = atom_add_acq_rel(&g_count[grp], 1u);
        slast = (old == (unsigned int)(nchunks - 1)) ? 1u : 0u;
    }
    slast = __shfl_sync(0xffffffffu, slast, 0);
    __syncwarp();                            // propagate lane0's acquire

    if (slast) {
        // Drain: each lane sums k=lane and k=lane+32 over the group's rows.
        float v0 = 0.0f, v1 = 0.0f;
        #pragma unroll 8
        for (int c = 0; c < nchunks; ++c) {
            v0 += g_part[row0 + c][lane];
            v1 += g_part[row0 + c][lane + 32];
        }
        out[b * (3 * KC) + outoff + lane]      = v0;
        out[b * (3 * KC) + outoff + lane + 32] = v1;
        if (lane == 0) g_count[grp] = 0u;    // reset for next graph replay
    }
}

extern "C" void kernel_launch(void* const* d_in, const int* in_sizes, int n_in,
                              void* d_out, int out_size)
{
    (void)in_sizes; (void)n_in; (void)out_size;
    const float* h0  = (const float*)d_in[0];
    const float* m0  = (const float*)d_in[1];
    const float* h0e = (const float*)d_in[2];
    const float* m0e = (const float*)d_in[3];
    const float* h1e = (const float*)d_in[4];
    const float* m1e = (const float*)d_in[5];
    const float* c0  = (const float*)d_in[6];
    const float* r0  = (const float*)d_in[7];
    const float* c0e = (const float*)d_in[8];
    const float* r0e = (const float*)d_in[9];
    const float* c1e = (const float*)d_in[10];
    const float* r1e = (const float*)d_in[11];
    float* out = (float*)d_out;

    pershom_kernel<<<NTILES, TPB>>>(h0, m0, h0e, m0e, h1e, m1e,
                                    c0, r0, c0e, r0e, c1e, r1e, out);
}